// round 17
// baseline (speedup 1.0000x reference)
#include <cuda_runtime.h>
#include <cuda_fp16.h>
#include <math_constants.h>
#include <cstdint>

#define NTOK 4096
#define CDIM 1024
#define BM 128
#define BN 128
#define BK 32
#define LDS_A 40    // K-major tile row stride (fp16): 80B, conflict-free ldmatrix
#define LDS_B 136   // trans-B tile row stride (fp16): 272B, conflict-free ldmatrix.trans
#define NTHR 128    // 4 warps, 2x2 of 64x64

// ---------------------------------------------------------------------------
// Scratch (__device__ globals; allocation-free rule)
// ---------------------------------------------------------------------------
__device__ __half g_xh[(size_t)NTOK * CDIM];
__device__ __half g_Wqh[(size_t)CDIM * CDIM];   // Wq fp16 as stored [n][i]
__device__ __half g_WkT[(size_t)CDIM * CDIM];   // Wk^T fp16 [i][n]
__device__ __half g_Wvh[(size_t)CDIM * CDIM];   // Wv fp16 as stored [j][i]
__device__ __half g_Woh[(size_t)CDIM * CDIM];   // Wo fp16 as stored [n][j]
__device__ __half g_T[(size_t)CDIM * CDIM];     // T[i][j] = sum_n Wk[n][i] Wq[n][j]
__device__ __half g_W2[(size_t)CDIM * CDIM];    // W2[n][i] = sum_j Wo[n][j] Wv[j][i]
__device__ __half g_G[(size_t)NTOK * CDIM];     // G = x M  (M = T^T)
__device__ float  g_S[(size_t)NTOK * NTOK];
__device__ __half g_P[(size_t)NTOK * NTOK];
__device__ float  g_Hp[4ULL * NTOK * CDIM];     // Y split-K partials (fp32)
__device__ __half g_H[(size_t)NTOK * CDIM];     // Y = P x (fp16)
__device__ float  g_u[CDIM];                    // Wk^T bq
__device__ float  g_c[NTOK];                    // x . u  (per-column softmax shift)
__device__ float  g_bo2[CDIM];                  // bo + Wo bv

// dependency counters (zero-initialized statically; reset by the in-kernel
// resetter block at the end of every launch)
__device__ int g_cnt[256];
#define C_U     0     // target 8
#define C_OBV   1     // target 8
#define C_C     2     // target 32
#define C_XALL  3     // target 512 (all x-convert blocks)
#define C_ODONE 4     // target 256 (all O blocks)
#define C_WQ    5     // target 128
#define C_WV    6     // target 128
#define C_WO    7     // target 128
#define C_TB    8     // 8 ctrs, target 8   (per T i-block)
#define C_W2B   16    // 8 ctrs, target 8   (per W2 n-block)
#define C_WKT   24    // 8 ctrs, target 32  (per WkT 128-row i-block)
#define C_GDONE 32    // 32 ctrs, target 8  (per G m-block)
#define C_SCNT  64    // 32 ctrs, target 32 (per S m-block)
#define C_PDONE 96    // 32 ctrs, target 8  (per m-block softmax chunks)
#define C_HRDY  128   // 32 ctrs, target 32 (per m-block Y tiles: 8 nb x 4 ks)
#define C_RDONE 160   // 32 ctrs, target 8  (per m-block reduce chunks)
#define C_XC    192   // 32 ctrs, target 16 (per x 128-row chunk)

// ---------------------------------------------------------------------------
// PTX helpers (sm_80-compatible only: cp.async / ldmatrix / mma.sync)
// ---------------------------------------------------------------------------
__device__ __forceinline__ uint32_t smem_u32(const void* p) {
    uint32_t a;
    asm("{ .reg .u64 t; cvta.to.shared.u64 t, %1; cvt.u32.u64 %0, t; }" : "=r"(a) : "l"(p));
    return a;
}

__device__ __forceinline__ void cpa16(uint32_t dst, const __half* src) {
    asm volatile("cp.async.cg.shared.global [%0], [%1], 16;" :: "r"(dst), "l"(src));
}
#define CP_COMMIT() asm volatile("cp.async.commit_group;")
#define CP_WAIT(n)  asm volatile("cp.async.wait_group %0;" :: "n"(n))

#define LDMX4(r, addr) \
    asm volatile("ldmatrix.sync.aligned.m8n8.x4.shared.b16 {%0,%1,%2,%3}, [%4];" \
                 : "=r"((r)[0]), "=r"((r)[1]), "=r"((r)[2]), "=r"((r)[3]) : "r"(addr))

#define LDMX4T(r, addr) \
    asm volatile("ldmatrix.sync.aligned.m8n8.x4.trans.shared.b16 {%0,%1,%2,%3}, [%4];" \
                 : "=r"((r)[0]), "=r"((r)[1]), "=r"((r)[2]), "=r"((r)[3]) : "r"(addr))

__device__ __forceinline__ void mma16816(float* c, const uint32_t* a, const uint32_t* b) {
    asm volatile(
        "mma.sync.aligned.m16n8k16.row.col.f32.f16.f16.f32 "
        "{%0,%1,%2,%3}, {%4,%5,%6,%7}, {%8,%9}, {%0,%1,%2,%3};"
        : "+f"(c[0]), "+f"(c[1]), "+f"(c[2]), "+f"(c[3])
        : "r"(a[0]), "r"(a[1]), "r"(a[2]), "r"(a[3]), "r"(b[0]), "r"(b[1]));
}

// ---------------------------------------------------------------------------
// sync helpers for the in-kernel DAG
// ---------------------------------------------------------------------------
__device__ __forceinline__ void spin_ge(int idx, int target) {
    volatile int* p = (volatile int*)&g_cnt[idx];
    if (threadIdx.x == 0) {
        while (*p < target) __nanosleep(128);
    }
    __syncthreads();
}
__device__ __forceinline__ void signal(int idx) {
    __threadfence();
    __syncthreads();
    if (threadIdx.x == 0) atomicAdd(&g_cnt[idx], 1);
}
__device__ __forceinline__ void signal2(int i1, int i2) {
    __threadfence();
    __syncthreads();
    if (threadIdx.x == 0) { atomicAdd(&g_cnt[i1], 1); atomicAdd(&g_cnt[i2], 1); }
}

// ---------------------------------------------------------------------------
// smem layout: two 128x32 K-major slots (A, B) per stage
// ---------------------------------------------------------------------------
#define TILE_B_BYTES (BM * LDS_A * 2)        // 10240 bytes per slot
#define STAGE_B (2 * TILE_B_BYTES)           // 20480
#define NSTAGE 3
#define SMEM_TOTAL (NSTAGE * STAGE_B)        // 61440  (2 CTAs/SM -> 120KB)

// K-major tile loader: 128 rows x 32 k, 128 threads -> 4 chunks each
__device__ __forceinline__ void load_km(uint32_t sbase, const __half* __restrict__ g,
                                        int row0, int stride, int kcol, int t) {
#pragma unroll
    for (int i = 0; i < 4; ++i) {
        int id = t + i * NTHR;
        int row = id >> 2, q = id & 3;
        cpa16(sbase + (uint32_t)(row * LDS_A + q * 8) * 2,
              g + (size_t)(row0 + row) * stride + kcol + q * 8);
    }
}

// trans-B tile loader: 32 rows (k) x 128 halves (n), n contiguous (stride CDIM)
__device__ __forceinline__ void load_bt(uint32_t sbase, const __half* __restrict__ g,
                                        int n0, int kc, int t) {
#pragma unroll
    for (int i = 0; i < 4; ++i) {
        int id = t + i * NTHR;         // 0..511
        int row = id >> 4;             // 0..31 (k)
        int q = id & 15;               // 16B chunk within 256B row
        cpa16(sbase + (uint32_t)(row * LDS_B + q * 8) * 2,
              g + (size_t)(kc + row) * CDIM + n0 + q * 8);
    }
}

// ---------------------------------------------------------------------------
// GEMM tile body: D[128,128] = A[m0.., :Klen] @ B^T
// BT: 0 = B K-major [n][k], 1 = B row-major [k][n] via ldmatrix.trans
// EPI: 0 = fp16 out (no bias), 1 = fp32 out, 2 = fp32 out + bias + resid
// 4 warps in 2x2, warp tile 64x64
// ---------------------------------------------------------------------------
template <int BT, int EPI>
__device__ __forceinline__ void gemm_body(
    const __half* __restrict__ Ah, const __half* __restrict__ Bg,
    const float* __restrict__ bias, const float* __restrict__ resid,
    __half* __restrict__ oh, float* __restrict__ of,
    int Klen, int Astride, int Bstride, int Nout, int m0, int n0, uint32_t sb)
{
    const int t = threadIdx.x;
    const int lane = t & 31;
    const int wid = t >> 5;            // 0..3
    const int nch = Klen / BK;

    const int warp_m = (wid & 1) * 64;
    const int warp_n = (wid >> 1) * 64;

    const uint32_t aoff = (uint32_t)((warp_m + (lane & 15)) * LDS_A + (lane >> 4) * 8) * 2;
    const uint32_t boff = (uint32_t)((warp_n + ((lane >> 4) & 1) * 8 + (lane & 7)) * LDS_A
                                     + ((lane >> 3) & 1) * 8) * 2;
    const uint32_t boffT = (uint32_t)(((((lane >> 3) & 1) * 8 + (lane & 7)) * LDS_B)
                                      + warp_n + (lane >> 4) * 8) * 2;

    float acc[4][8][4];
#pragma unroll
    for (int i = 0; i < 4; ++i)
#pragma unroll
        for (int j = 0; j < 8; ++j)
#pragma unroll
            for (int r = 0; r < 4; ++r) acc[i][j][r] = 0.0f;

#pragma unroll
    for (int s = 0; s < 2; ++s) {
        uint32_t sg = sb + s * STAGE_B;
        int kc = s * BK;
        load_km(sg, Ah, m0, Astride, kc, t);
        if (BT) load_bt(sg + TILE_B_BYTES, Bg, n0, kc, t);
        else    load_km(sg + TILE_B_BYTES, Bg, n0, Bstride, kc, t);
        CP_COMMIT();
    }

    int slot = 0, slot2 = 2;
    for (int c = 0; c < nch; ++c) {
        if (c + 1 < nch) { CP_WAIT(1); } else { CP_WAIT(0); }
        __syncthreads();

        if (c + 2 < nch) {
            uint32_t sg = sb + slot2 * STAGE_B;
            int kc = (c + 2) * BK;
            load_km(sg, Ah, m0, Astride, kc, t);
            if (BT) load_bt(sg + TILE_B_BYTES, Bg, n0, kc, t);
            else    load_km(sg + TILE_B_BYTES, Bg, n0, Bstride, kc, t);
            CP_COMMIT();
        }

        const uint32_t s0 = sb + slot * STAGE_B;
#pragma unroll
        for (int s = 0; s < 2; ++s) {
            uint32_t ah[4][4], bh[8][2];
#pragma unroll
            for (int i = 0; i < 4; ++i) {
                const uint32_t ao = (uint32_t)(i * 16 * LDS_A + s * 16) * 2;
                LDMX4(ah[i], s0 + aoff + ao);
            }
#pragma unroll
            for (int g = 0; g < 4; ++g) {
                uint32_t r[4];
                if (BT) {
                    const uint32_t bo = (uint32_t)(s * 16 * LDS_B + g * 16) * 2;
                    LDMX4T(r, s0 + TILE_B_BYTES + boffT + bo);
                } else {
                    const uint32_t bo = (uint32_t)(g * 16 * LDS_A + s * 16) * 2;
                    LDMX4(r, s0 + TILE_B_BYTES + boff + bo);
                }
                bh[2 * g][0] = r[0]; bh[2 * g][1] = r[1];
                bh[2 * g + 1][0] = r[2]; bh[2 * g + 1][1] = r[3];
            }
#pragma unroll
            for (int i = 0; i < 4; ++i)
#pragma unroll
                for (int j = 0; j < 8; ++j)
                    mma16816(acc[i][j], ah[i], bh[j]);
        }
        slot = (slot + 1 == NSTAGE) ? 0 : slot + 1;
        slot2 = (slot2 + 1 == NSTAGE) ? 0 : slot2 + 1;
    }

    // epilogue
#pragma unroll
    for (int i = 0; i < 4; ++i) {
        const int r0 = m0 + warp_m + i * 16 + (lane >> 2);
        const int r1 = r0 + 8;
#pragma unroll
        for (int j = 0; j < 8; ++j) {
            const int cc = n0 + warp_n + j * 8 + (lane & 3) * 2;
            float v0 = acc[i][j][0], v1 = acc[i][j][1];
            float v2 = acc[i][j][2], v3 = acc[i][j][3];

            if (EPI == 1) {
                *(float2*)(of + (size_t)r0 * Nout + cc) = make_float2(v0, v1);
                *(float2*)(of + (size_t)r1 * Nout + cc) = make_float2(v2, v3);
            } else if (EPI == 2) {
                const float b0 = bias[cc], b1 = bias[cc + 1];
                float2 ra = *(const float2*)(resid + (size_t)r0 * Nout + cc);
                float2 rb = *(const float2*)(resid + (size_t)r1 * Nout + cc);
                *(float2*)(of + (size_t)r0 * Nout + cc) = make_float2(v0 + b0 + ra.x, v1 + b1 + ra.y);
                *(float2*)(of + (size_t)r1 * Nout + cc) = make_float2(v2 + b0 + rb.x, v3 + b1 + rb.y);
            } else {
                *(__half2*)(oh + (size_t)r0 * Nout + cc) =
                    __halves2half2(__float2half_rn(v0), __float2half_rn(v1));
                *(__half2*)(oh + (size_t)r1 * Nout + cc) =
                    __halves2half2(__float2half_rn(v2), __float2half_rn(v3));
            }
        }
    }
}

// ---------------------------------------------------------------------------
// softmax body: 16 rows, 128 threads, fp32 S (+ per-column shift c) -> fp16 P
// ---------------------------------------------------------------------------
__device__ __forceinline__ float warpMax(float v) {
#pragma unroll
    for (int o = 16; o > 0; o >>= 1) v = fmaxf(v, __shfl_xor_sync(0xffffffffu, v, o));
    return v;
}
__device__ __forceinline__ float warpSum(float v) {
#pragma unroll
    for (int o = 16; o > 0; o >>= 1) v += __shfl_xor_sync(0xffffffffu, v, o);
    return v;
}

__device__ void softmax_body(const float* __restrict__ S, __half* __restrict__ P,
                             int row0, char* smemraw) {
    float* red = (float*)smemraw;
    const int t = threadIdx.x;
    const int lane = t & 31, wid = t >> 5;

    float4 cs[8];
#pragma unroll
    for (int i = 0; i < 8; ++i) cs[i] = ((const float4*)g_c)[t + NTHR * i];

    for (int r = 0; r < 16; ++r) {
        const int row = row0 + r;
        const float4* pr = (const float4*)(S + (size_t)row * NTOK);
        float4 v[8];
#pragma unroll
        for (int i = 0; i < 8; ++i) {
            v[i] = pr[t + NTHR * i];
            v[i].x += cs[i].x; v[i].y += cs[i].y;
            v[i].z += cs[i].z; v[i].w += cs[i].w;
        }

        float m = -CUDART_INF_F;
#pragma unroll
        for (int i = 0; i < 8; ++i)
            m = fmaxf(m, fmaxf(fmaxf(v[i].x, v[i].y), fmaxf(v[i].z, v[i].w)));
        m = warpMax(m);
        if (lane == 0) red[wid] = m;
        __syncthreads();
        if (t < 32) {
            float z = (t < 4) ? red[t] : -CUDART_INF_F;
            z = warpMax(z);
            if (t == 0) red[4] = z;
        }
        __syncthreads();
        m = red[4];

        float s = 0.0f;
#pragma unroll
        for (int i = 0; i < 8; ++i) {
            v[i].x = __expf(v[i].x - m); v[i].y = __expf(v[i].y - m);
            v[i].z = __expf(v[i].z - m); v[i].w = __expf(v[i].w - m);
            s += (v[i].x + v[i].y) + (v[i].z + v[i].w);
        }
        s = warpSum(s);
        __syncthreads();
        if (lane == 0) red[wid] = s;
        __syncthreads();
        if (t < 32) {
            float z = (t < 4) ? red[t] : 0.0f;
            z = warpSum(z);
            if (t == 0) red[4] = z;
        }
        __syncthreads();
        const float inv = 1.0f / red[4];

        uint2* po = (uint2*)(P + (size_t)row * NTOK);
#pragma unroll
        for (int i = 0; i < 8; ++i) {
            __half2 h0 = __floats2half2_rn(v[i].x * inv, v[i].y * inv);
            __half2 h1 = __floats2half2_rn(v[i].z * inv, v[i].w * inv);
            uint2 u;
            u.x = *(uint32_t*)&h0;
            u.y = *(uint32_t*)&h1;
            po[t + NTHR * i] = u;
        }
        __syncthreads();
    }
}

// ---------------------------------------------------------------------------
// H reduce body: H = sum of 4 fp32 partials -> fp16.  16 rows, 128 threads.
// ---------------------------------------------------------------------------
__device__ void reduce_body(const float* __restrict__ Hp, __half* __restrict__ H, int row0) {
    const int t = threadIdx.x;
    const size_t plane = (size_t)NTOK * CDIM;
    for (int r = 0; r < 16; ++r) {
        const int row = row0 + r;
#pragma unroll
        for (int i = 0; i < 2; ++i) {
            const int col = t + i * NTHR;
            const float4* h0 = (const float4*)(Hp + (size_t)row * CDIM);
            const float4* h1 = (const float4*)(Hp + plane + (size_t)row * CDIM);
            const float4* h2 = (const float4*)(Hp + 2 * plane + (size_t)row * CDIM);
            const float4* h3 = (const float4*)(Hp + 3 * plane + (size_t)row * CDIM);
            float4 a = h0[col], b = h1[col], c = h2[col], d = h3[col];
            __half2 p0 = __floats2half2_rn(a.x + b.x + c.x + d.x, a.y + b.y + c.y + d.y);
            __half2 p1 = __floats2half2_rn(a.z + b.z + c.z + d.z, a.w + b.w + c.w + d.w);
            uint2 u;
            u.x = *(uint32_t*)&p0;
            u.y = *(uint32_t*)&p1;
            ((uint2*)(H + (size_t)row * CDIM))[col] = u;
        }
    }
}

// ---------------------------------------------------------------------------
// small-GEMV body: out[i] = base(i) + dot(Wrow_fp16[i][:], vec_fp32)
// ---------------------------------------------------------------------------
__device__ void gemv_body(const __half* __restrict__ W, const float* __restrict__ vec,
                          const float* __restrict__ base, float* __restrict__ out, int i0) {
    const int i = i0 + threadIdx.x;
    const __half2* w = (const __half2*)(W + (size_t)i * CDIM);
    float acc = 0.0f;
    for (int o = 0; o < CDIM / 2; ++o) {
        float2 wv = __half22float2(w[o]);
        acc += wv.x * vec[2 * o] + wv.y * vec[2 * o + 1];
    }
    out[i] = (base ? base[i] : 0.0f) + acc;
}

// ---------------------------------------------------------------------------
// convert body: 2048 float4 -> 8192 fp16 per block (128 threads, 16 iters)
// ---------------------------------------------------------------------------
__device__ void cvt_body(const float4* __restrict__ in, __half* __restrict__ out, int blk) {
    const int t = threadIdx.x;
#pragma unroll
    for (int i = 0; i < 16; ++i) {
        int k = blk * 2048 + t + i * NTHR;
        float4 v = in[k];
        *(__half2*)(out + (size_t)k * 4)     = __floats2half2_rn(v.x, v.y);
        *(__half2*)(out + (size_t)k * 4 + 2) = __floats2half2_rn(v.z, v.w);
    }
}

// ---------------------------------------------------------------------------
// Wk transpose-convert body: one 64x64 tile, 128 threads
// ---------------------------------------------------------------------------
__device__ void wkT_body(const float* __restrict__ wk, __half* __restrict__ wkT,
                         int tile, char* smemraw) {
    float (*s)[65] = (float(*)[65])smemraw;
    const int ti = tile >> 4, tj = tile & 15;
    const int t = threadIdx.x;
#pragma unroll
    for (int i = 0; i < 8; ++i) {
        int id = t + i * NTHR;
        int rl = id >> 4, cq = (id & 15) * 4;
        float4 v = *(const float4*)&wk[(size_t)(ti * 64 + rl) * CDIM + tj * 64 + cq];
        s[rl][cq] = v.x; s[rl][cq + 1] = v.y; s[rl][cq + 2] = v.z; s[rl][cq + 3] = v.w;
    }
    __syncthreads();
#pragma unroll
    for (int i = 0; i < 4; ++i) {
        int id = t + i * NTHR;
        int rr = id >> 3, qq = id & 7;
        __half h[8];
#pragma unroll
        for (int j = 0; j < 8; ++j) h[j] = __float2half_rn(s[qq * 8 + j][rr]);
        *(uint4*)&wkT[(size_t)(tj * 64 + rr) * CDIM + ti * 64 + qq * 8] = *(uint4*)h;
    }
}

// ---------------------------------------------------------------------------
// Mega kernel (the WHOLE computation, one launch). Roles by blockIdx.x:
//  [0,128)      Wq cvt          [128,256)  Wv cvt       [256,384) Wo cvt
//  [384,640)    WkT transpose   [640,1152) x cvt
//  [1152,1160)  u = Wk^T bq     [1160,1168) bo2 = bo + Wo bv
//  [1168,1232)  T = WkT x Wq    [1232,1296) W2 = Wo x Wv
//  [1296,1552)  G = x M         [1552,1584) c = x . u
//  [1584,2608)  S = G x^T       [2608,2864) softmax(+c)
//  [2864,3888)  Y = P x (split-K x4)
//  [3888,4144)  reduce          [4144,4400) O = x + Y W2^T + bo2
//  4400         counter resetter
// ---------------------------------------------------------------------------
struct MegaArgs {
    const float *x, *wk, *bq, *bv, *bo;
    const float4 *x4, *wq4, *wv4, *wo4;
    float* out;
};
#define MEGA_GRID 4401

__global__ __launch_bounds__(NTHR, 2) void mega(const MegaArgs a) {
    extern __shared__ char smem[];
    const uint32_t sb = smem_u32(smem);
    const int b = blockIdx.x;

    if (b < 128) {                       // Wq convert
        cvt_body(a.wq4, g_Wqh, b);
        signal(C_WQ);
    } else if (b < 256) {                // Wv convert
        cvt_body(a.wv4, g_Wvh, b - 128);
        signal(C_WV);
    } else if (b < 384) {                // Wo convert
        cvt_body(a.wo4, g_Woh, b - 256);
        signal(C_WO);
    } else if (b < 640) {                // Wk transpose-convert
        const int tile = b - 384;
        wkT_body(a.wk, g_WkT, tile, smem);
        signal(C_WKT + ((tile & 15) >> 1));
    } else if (b < 1152) {               // x convert
        const int i = b - 640;
        cvt_body(a.x4, g_xh, i);
        signal2(C_XC + (i >> 4), C_XALL);
    } else if (b < 1160) {               // u = Wk^T bq
        const int i = b - 1152;
        spin_ge(C_WKT + i, 32);
        gemv_body(g_WkT, a.bq, nullptr, g_u, i * NTHR);
        signal(C_U);
    } else if (b < 1168) {               // bo2 = bo + Wo bv
        spin_ge(C_WO, 128);
        gemv_body(g_Woh, a.bv, a.bo, g_bo2, (b - 1160) * NTHR);
        signal(C_OBV);
    } else if (b < 1232) {               // T[i][j] = sum_n WkT[i][n] Wq[n][j]  (BT)
        const int i = b - 1168, tb = i >> 3, nb = i & 7;
        spin_ge(C_WKT + tb, 32);
        spin_ge(C_WQ, 128);
        gemm_body<1, 0>(g_WkT, g_Wqh, nullptr, nullptr, g_T, nullptr,
                        CDIM, CDIM, 0, CDIM, tb * 128, nb * 128, sb);
        signal(C_TB + tb);
    } else if (b < 1296) {               // W2[n][i] = sum_j Wo[n][j] Wv[j][i]  (BT)
        const int i = b - 1232, tb = i >> 3, nb = i & 7;
        spin_ge(C_WO, 128);
        spin_ge(C_WV, 128);
        gemm_body<1, 0>(g_Woh, g_Wvh, nullptr, nullptr, g_W2, nullptr,
                        CDIM, CDIM, 0, CDIM, tb * 128, nb * 128, sb);
        signal(C_W2B + tb);
    } else if (b < 1552) {               // G = x M
        const int i = b - 1296, gb = i >> 3, nb = i & 7;
        spin_ge(C_TB + nb, 8);
        spin_ge(C_XC + gb, 16);
        gemm_body<0, 0>(g_xh, g_T, nullptr, nullptr, g_G, nullptr,
                        CDIM, CDIM, CDIM, CDIM, gb * 128, nb * 128, sb);
        signal(C_GDONE + gb);
    } else if (b < 1584) {               // c[n] = dot(xh[n], u)
        const int i = b - 1552;
        spin_ge(C_U, 8);
        spin_ge(C_XALL, 512);
        gemv_body(g_xh, g_u, nullptr, g_c, i * NTHR);
        signal(C_C);
    } else if (b < 2608) {               // S = G x^T (fp32)
        const int i = b - 1584, mb = i >> 5, nb = i & 31;
        spin_ge(C_GDONE + mb, 8);
        spin_ge(C_XC + nb, 16);
        gemm_body<0, 1>(g_G, g_xh, nullptr, nullptr, nullptr, g_S,
                        CDIM, CDIM, CDIM, NTOK, mb * 128, nb * 128, sb);
        signal(C_SCNT + mb);
    } else if (b < 2864) {               // softmax(+c)
        const int i = b - 2608, mb = i >> 3, rq = i & 7;
        spin_ge(C_SCNT + mb, 32);
        spin_ge(C_C, 32);
        softmax_body(g_S, g_P, mb * 128 + rq * 16, smem);
        signal(C_PDONE + mb);
    } else if (b < 3888) {               // Y = P x  (split-K x4)
        const int i = b - 2864, mb = i >> 5, r = i & 31;
        const int nb = r >> 2, ks = r & 3;
        spin_ge(C_PDONE + mb, 8);
        spin_ge(C_XALL, 512);
        gemm_body<1, 1>(g_P + ks * 1024, g_xh + (size_t)ks * 1024 * CDIM,
                        nullptr, nullptr, nullptr, g_Hp + (size_t)ks * NTOK * CDIM,
                        1024, NTOK, 0, CDIM, mb * 128, nb * 128, sb);
        signal(C_HRDY + mb);
    } else if (b < 4144) {               // reduce
        const int i = b - 3888, mb = i >> 3, rq = i & 7;
        spin_ge(C_HRDY + mb, 32);
        reduce_body(g_Hp, g_H, mb * 128 + rq * 16);
        signal(C_RDONE + mb);
    } else if (b < 4400) {               // O = x + Y W2^T + bo2
        const int i = b - 4144, mb = i >> 3, nb = i & 7;
        spin_ge(C_RDONE + mb, 8);
        spin_ge(C_W2B + nb, 8);
        spin_ge(C_OBV, 8);
        gemm_body<0, 2>(g_H, g_W2, g_bo2, a.x, nullptr, a.out,
                        CDIM, CDIM, CDIM, CDIM, mb * 128, nb * 128, sb);
        signal(C_ODONE);
    } else {                             // resetter: zero counters for next launch
        spin_ge(C_ODONE, 256);
        g_cnt[threadIdx.x] = 0;
        g_cnt[threadIdx.x + 128] = 0;
    }
}

// ---------------------------------------------------------------------------
// Launch
// ---------------------------------------------------------------------------
extern "C" void kernel_launch(void* const* d_in, const int* in_sizes, int n_in,
                              void* d_out, int out_size) {
    const float* x  = (const float*)d_in[0];
    const float* Wq = (const float*)d_in[1];
    const float* bq = (const float*)d_in[2];
    const float* Wk = (const float*)d_in[3];
    const float* Wv = (const float*)d_in[5];
    const float* bv = (const float*)d_in[6];
    const float* Wo = (const float*)d_in[7];
    const float* bo = (const float*)d_in[8];
    float* out = (float*)d_out;

    cudaFuncSetAttribute(mega, cudaFuncAttributeMaxDynamicSharedMemorySize, SMEM_TOTAL);

    MegaArgs ma;
    ma.x = x; ma.wk = Wk; ma.bq = bq; ma.bv = bv; ma.bo = bo;
    ma.x4 = (const float4*)x; ma.wq4 = (const float4*)Wq;
    ma.wv4 = (const float4*)Wv; ma.wo4 = (const float4*)Wo;
    ma.out = out;
    mega<<<MEGA_GRID, NTHR, SMEM_TOTAL>>>(ma);
}